// round 2
// baseline (speedup 1.0000x reference)
#include <cuda_runtime.h>
#include <math.h>

// Problem constants (fixed by reference)
#define VOCAB 100000
#define DIM   128
#define BATCH 16384
#define CTX   10
#define NEG   5

#define WARPS_PER_BLOCK 8
#define THREADS (WARPS_PER_BLOCK * 32)
#define NUM_BLOCKS (BATCH / WARPS_PER_BLOCK)   // 2048

// Scratch (no cudaMalloc allowed)
__device__ float        g_partials[NUM_BLOCKS];
__device__ unsigned int g_ticket = 0;

__device__ __forceinline__ float log_sigmoid(float x) {
    // stable: min(x,0) - log1p(exp(-|x|))
    return fminf(x, 0.0f) - log1pf(expf(-fabsf(x)));
}

__global__ __launch_bounds__(THREADS)
void cbow_loss_fused(const int* __restrict__ pos_u,   // [B, CTX]
                     const int* __restrict__ pos_w,   // [B]
                     const int* __restrict__ neg_w,   // [B, NEG]
                     const float4* __restrict__ u_w,  // [VOCAB, 32] as float4
                     const float4* __restrict__ w_w,  // [VOCAB, 32] as float4
                     float* __restrict__ out)
{
    const int warp = threadIdx.x >> 5;
    const int lane = threadIdx.x & 31;
    const int b = blockIdx.x * WARPS_PER_BLOCK + warp;

    // ---- load all 16 indices up front ----
    const int* pu = pos_u + b * CTX;
    int ui[CTX], ni[NEG];
    #pragma unroll
    for (int c = 0; c < CTX; ++c) ui[c] = __ldg(pu + c);
    const int pi = __ldg(pos_w + b);
    const int* nw = neg_w + b * NEG;
    #pragma unroll
    for (int k = 0; k < NEG; ++k) ni[k] = __ldg(nw + k);

    // ---- 16 independent row gathers, 3 accumulators (max MLP) ----
    float4 usum = make_float4(0.f, 0.f, 0.f, 0.f);
    float4 nsum = make_float4(0.f, 0.f, 0.f, 0.f);
    float4 p = __ldg(w_w + (size_t)pi * 32 + lane);
    #pragma unroll
    for (int k = 0; k < NEG; ++k) {
        float4 v = __ldg(w_w + (size_t)ni[k] * 32 + lane);
        nsum.x += v.x; nsum.y += v.y; nsum.z += v.z; nsum.w += v.w;
    }
    #pragma unroll
    for (int c = 0; c < CTX; ++c) {
        float4 v = __ldg(u_w + (size_t)ui[c] * 32 + lane);
        usum.x += v.x; usum.y += v.y; usum.z += v.z; usum.w += v.w;
    }

    float pd = usum.x * p.x + usum.y * p.y + usum.z * p.z + usum.w * p.w;
    float nd = usum.x * nsum.x + usum.y * nsum.y + usum.z * nsum.z + usum.w * nsum.w;

    // ---- warp reduce both dots ----
    #pragma unroll
    for (int off = 16; off > 0; off >>= 1) {
        pd += __shfl_xor_sync(0xFFFFFFFFu, pd, off);
        nd += __shfl_xor_sync(0xFFFFFFFFu, nd, off);
    }

    __shared__ float s_part[WARPS_PER_BLOCK];
    if (lane == 0)
        s_part[warp] = log_sigmoid(pd) + log_sigmoid(-nd);
    __syncthreads();

    __shared__ bool s_last;
    if (threadIdx.x == 0) {
        float acc = 0.f;
        #pragma unroll
        for (int i = 0; i < WARPS_PER_BLOCK; ++i) acc += s_part[i];
        g_partials[blockIdx.x] = acc;
        __threadfence();
        unsigned int t = atomicAdd(&g_ticket, 1u);
        s_last = (t == NUM_BLOCKS - 1);
    }
    __syncthreads();

    // ---- last block does the deterministic final reduce ----
    if (s_last) {
        const int tid = threadIdx.x;
        double acc = 0.0;
        #pragma unroll 4
        for (int i = tid; i < NUM_BLOCKS; i += THREADS)
            acc += (double)g_partials[i];

        #pragma unroll
        for (int off = 16; off > 0; off >>= 1)
            acc += __shfl_xor_sync(0xFFFFFFFFu, acc, off);

        __shared__ double s[WARPS_PER_BLOCK];
        if (lane == 0) s[warp] = acc;
        __syncthreads();
        if (tid == 0) {
            double t = 0.0;
            #pragma unroll
            for (int i = 0; i < WARPS_PER_BLOCK; ++i) t += s[i];
            out[0] = (float)(-t);     // loss = -(sum of logsigmoids)
            g_ticket = 0;             // reset for next graph replay
        }
    }
}

extern "C" void kernel_launch(void* const* d_in, const int* in_sizes, int n_in,
                              void* d_out, int out_size) {
    const int*    pos_u = (const int*)d_in[0];
    const int*    pos_w = (const int*)d_in[1];
    const int*    neg_w = (const int*)d_in[2];
    const float4* u_w   = (const float4*)d_in[3];
    const float4* w_w   = (const float4*)d_in[4];
    float* out = (float*)d_out;

    cbow_loss_fused<<<NUM_BLOCKS, THREADS>>>(pos_u, pos_w, neg_w, u_w, w_w, out);
}

// round 4
// speedup vs baseline: 1.2411x; 1.2411x over previous
#include <cuda_runtime.h>
#include <math.h>

// Problem constants (fixed by reference)
#define VOCAB 100000
#define DIM   128
#define BATCH 16384
#define CTX   10
#define NEG   5

#define WARPS_PER_BLOCK 8
#define THREADS (WARPS_PER_BLOCK * 32)
#define NUM_BLOCKS (BATCH / WARPS_PER_BLOCK)   // 2048

// Scratch (no cudaMalloc allowed)
__device__ double       g_accum  = 0.0;
__device__ unsigned int g_ticket = 0;

__device__ __forceinline__ float log_sigmoid(float x) {
    // stable: min(x,0) - log1p(exp(-|x|))
    return fminf(x, 0.0f) - log1pf(expf(-fabsf(x)));
}

// Create an L2 "evict_last" access policy once; apply it to every table load
// via ld.global.nc.L2::cache_hint (legal for v4.f32, unlike the inline
// .L2::evict_last qualifier which sm_103 ptxas restricts to 256-bit loads).
__device__ __forceinline__ unsigned long long make_keep_policy() {
    unsigned long long pol;
    asm("createpolicy.fractional.L2::evict_last.b64 %0, 1.0;" : "=l"(pol));
    return pol;
}

__device__ __forceinline__ float4 ldg_keep(const float4* p, unsigned long long pol) {
    float4 v;
    asm("ld.global.nc.L2::cache_hint.v4.f32 {%0,%1,%2,%3}, [%4], %5;"
        : "=f"(v.x), "=f"(v.y), "=f"(v.z), "=f"(v.w)
        : "l"(p), "l"(pol));
    return v;
}

__global__ __launch_bounds__(THREADS)
void cbow_loss_fused(const int* __restrict__ pos_u,   // [B, CTX]
                     const int* __restrict__ pos_w,   // [B]
                     const int* __restrict__ neg_w,   // [B, NEG]
                     const float4* __restrict__ u_w,  // [VOCAB, 32] as float4
                     const float4* __restrict__ w_w,  // [VOCAB, 32] as float4
                     float* __restrict__ out)
{
    const int warp = threadIdx.x >> 5;
    const int lane = threadIdx.x & 31;
    const int b = blockIdx.x * WARPS_PER_BLOCK + warp;

    const unsigned long long pol = make_keep_policy();

    // --- gather-sum context embeddings ---
    float4 usum = make_float4(0.f, 0.f, 0.f, 0.f);
    const int* pu = pos_u + b * CTX;
    #pragma unroll
    for (int c = 0; c < CTX; ++c) {
        int idx = __ldg(pu + c);                         // uniform across warp
        float4 v = ldg_keep(u_w + (size_t)idx * 32 + lane, pol);
        usum.x += v.x; usum.y += v.y; usum.z += v.z; usum.w += v.w;
    }

    // --- positive target row ---
    int pidx = __ldg(pos_w + b);
    float4 p = ldg_keep(w_w + (size_t)pidx * 32 + lane, pol);
    float pd = usum.x * p.x + usum.y * p.y + usum.z * p.z + usum.w * p.w;

    // --- negative rows summed first (dot distributes over the sum) ---
    float4 nsum = make_float4(0.f, 0.f, 0.f, 0.f);
    const int* nw = neg_w + b * NEG;
    #pragma unroll
    for (int k = 0; k < NEG; ++k) {
        int idx = __ldg(nw + k);
        float4 v = ldg_keep(w_w + (size_t)idx * 32 + lane, pol);
        nsum.x += v.x; nsum.y += v.y; nsum.z += v.z; nsum.w += v.w;
    }
    float nd = usum.x * nsum.x + usum.y * nsum.y + usum.z * nsum.z + usum.w * nsum.w;

    // --- warp reduce both dots together ---
    #pragma unroll
    for (int off = 16; off > 0; off >>= 1) {
        pd += __shfl_xor_sync(0xFFFFFFFFu, pd, off);
        nd += __shfl_xor_sync(0xFFFFFFFFu, nd, off);
    }

    __shared__ float s_part[WARPS_PER_BLOCK];
    if (lane == 0)
        s_part[warp] = log_sigmoid(pd) + log_sigmoid(-nd);
    __syncthreads();

    // --- featherweight epilogue: one double atomic per block + ticket ---
    if (threadIdx.x == 0) {
        float acc = 0.f;
        #pragma unroll
        for (int i = 0; i < WARPS_PER_BLOCK; ++i) acc += s_part[i];
        atomicAdd(&g_accum, (double)acc);   // order-insensitive in double
        __threadfence();                    // release before ticket
        unsigned int t = atomicAdd(&g_ticket, 1u);
        if (t == NUM_BLOCKS - 1) {
            __threadfence();                // acquire after last ticket
            double total = g_accum;
            out[0] = (float)(-total);       // loss = -(sum of logsigmoids)
            g_accum  = 0.0;                 // reset for next graph replay
            g_ticket = 0;
        }
    }
}

extern "C" void kernel_launch(void* const* d_in, const int* in_sizes, int n_in,
                              void* d_out, int out_size) {
    const int*    pos_u = (const int*)d_in[0];
    const int*    pos_w = (const int*)d_in[1];
    const int*    neg_w = (const int*)d_in[2];
    const float4* u_w   = (const float4*)d_in[3];
    const float4* w_w   = (const float4*)d_in[4];
    float* out = (float*)d_out;

    cbow_loss_fused<<<NUM_BLOCKS, THREADS>>>(pos_u, pos_w, neg_w, u_w, w_w, out);
}

// round 5
// speedup vs baseline: 1.2576x; 1.0133x over previous
#include <cuda_runtime.h>
#include <math.h>

// Problem constants (fixed by reference)
#define VOCAB 100000
#define DIM   128
#define BATCH 16384
#define CTX   10
#define NEG   5

#define WARPS_PER_BLOCK 8
#define THREADS (WARPS_PER_BLOCK * 32)
#define NUM_BLOCKS (BATCH / WARPS_PER_BLOCK)   // 2048

// Scratch (no cudaMalloc allowed)
__device__ double       g_accum  = 0.0;
__device__ unsigned int g_ticket = 0;

__device__ __forceinline__ float log_sigmoid(float x) {
    // stable: min(x,0) - log1p(exp(-|x|))
    return fminf(x, 0.0f) - log1pf(expf(-fabsf(x)));
}

// Asymmetric L2 policy:
//  - u_weight (51.2 MB, 80.6k unique rows/replay) -> evict_last: fits the L2
//    persisting carveout, so replays hit in L2.
//  - w_weight -> evict_first: streamed, never pollutes the carveout.
__device__ __forceinline__ unsigned long long make_policy_keep() {
    unsigned long long pol;
    asm("createpolicy.fractional.L2::evict_last.b64 %0, 1.0;" : "=l"(pol));
    return pol;
}
__device__ __forceinline__ unsigned long long make_policy_stream() {
    unsigned long long pol;
    asm("createpolicy.fractional.L2::evict_first.b64 %0, 1.0;" : "=l"(pol));
    return pol;
}

__device__ __forceinline__ float4 ldg_pol(const float4* p, unsigned long long pol) {
    float4 v;
    asm("ld.global.nc.L2::cache_hint.v4.f32 {%0,%1,%2,%3}, [%4], %5;"
        : "=f"(v.x), "=f"(v.y), "=f"(v.z), "=f"(v.w)
        : "l"(p), "l"(pol));
    return v;
}

__global__ __launch_bounds__(THREADS)
void cbow_loss_fused(const int* __restrict__ pos_u,   // [B, CTX]
                     const int* __restrict__ pos_w,   // [B]
                     const int* __restrict__ neg_w,   // [B, NEG]
                     const float4* __restrict__ u_w,  // [VOCAB, 32] as float4
                     const float4* __restrict__ w_w,  // [VOCAB, 32] as float4
                     float* __restrict__ out)
{
    const int warp = threadIdx.x >> 5;
    const int lane = threadIdx.x & 31;
    const int b = blockIdx.x * WARPS_PER_BLOCK + warp;

    const unsigned long long pol_keep   = make_policy_keep();
    const unsigned long long pol_stream = make_policy_stream();

    // --- gather-sum context embeddings (u-table: pinned in L2) ---
    float4 usum = make_float4(0.f, 0.f, 0.f, 0.f);
    const int* pu = pos_u + b * CTX;
    #pragma unroll
    for (int c = 0; c < CTX; ++c) {
        int idx = __ldg(pu + c);                         // uniform across warp
        float4 v = ldg_pol(u_w + (size_t)idx * 32 + lane, pol_keep);
        usum.x += v.x; usum.y += v.y; usum.z += v.z; usum.w += v.w;
    }

    // --- positive target row (w-table: streamed) ---
    int pidx = __ldg(pos_w + b);
    float4 p = ldg_pol(w_w + (size_t)pidx * 32 + lane, pol_stream);
    float pd = usum.x * p.x + usum.y * p.y + usum.z * p.z + usum.w * p.w;

    // --- negative rows summed first (dot distributes over the sum) ---
    float4 nsum = make_float4(0.f, 0.f, 0.f, 0.f);
    const int* nw = neg_w + b * NEG;
    #pragma unroll
    for (int k = 0; k < NEG; ++k) {
        int idx = __ldg(nw + k);
        float4 v = ldg_pol(w_w + (size_t)idx * 32 + lane, pol_stream);
        nsum.x += v.x; nsum.y += v.y; nsum.z += v.z; nsum.w += v.w;
    }
    float nd = usum.x * nsum.x + usum.y * nsum.y + usum.z * nsum.z + usum.w * nsum.w;

    // --- warp reduce both dots together ---
    #pragma unroll
    for (int off = 16; off > 0; off >>= 1) {
        pd += __shfl_xor_sync(0xFFFFFFFFu, pd, off);
        nd += __shfl_xor_sync(0xFFFFFFFFu, nd, off);
    }

    __shared__ float s_part[WARPS_PER_BLOCK];
    if (lane == 0)
        s_part[warp] = log_sigmoid(pd) + log_sigmoid(-nd);
    __syncthreads();

    // --- featherweight epilogue: one double atomic per block + ticket ---
    if (threadIdx.x == 0) {
        float acc = 0.f;
        #pragma unroll
        for (int i = 0; i < WARPS_PER_BLOCK; ++i) acc += s_part[i];
        atomicAdd(&g_accum, (double)acc);   // order-insensitive in double
        __threadfence();                    // release before ticket
        unsigned int t = atomicAdd(&g_ticket, 1u);
        if (t == NUM_BLOCKS - 1) {
            __threadfence();                // acquire after last ticket
            double total = g_accum;
            out[0] = (float)(-total);       // loss = -(sum of logsigmoids)
            g_accum  = 0.0;                 // reset for next graph replay
            g_ticket = 0;
        }
    }
}

extern "C" void kernel_launch(void* const* d_in, const int* in_sizes, int n_in,
                              void* d_out, int out_size) {
    const int*    pos_u = (const int*)d_in[0];
    const int*    pos_w = (const int*)d_in[1];
    const int*    neg_w = (const int*)d_in[2];
    const float4* u_w   = (const float4*)d_in[3];
    const float4* w_w   = (const float4*)d_in[4];
    float* out = (float*)d_out;

    cbow_loss_fused<<<NUM_BLOCKS, THREADS>>>(pos_u, pos_w, neg_w, u_w, w_w, out);
}

// round 6
// speedup vs baseline: 1.4038x; 1.1163x over previous
#include <cuda_runtime.h>
#include <math.h>

// Problem constants (fixed by reference)
#define VOCAB 100000
#define DIM   128
#define BATCH 16384
#define CTX   10
#define NEG   5

#define WARPS_PER_BLOCK 8
#define THREADS (WARPS_PER_BLOCK * 32)
#define ELEMS_PER_WARP 2
#define NUM_BLOCKS (BATCH / (WARPS_PER_BLOCK * ELEMS_PER_WARP))   // 1024: single CTA wave

// Scratch (no cudaMalloc allowed)
__device__ double       g_accum  = 0.0;
__device__ unsigned int g_ticket = 0;

__device__ __forceinline__ float log_sigmoid(float x) {
    // stable: min(x,0) - log1p(exp(-|x|))
    return fminf(x, 0.0f) - log1pf(expf(-fabsf(x)));
}

// Asymmetric L2 policy: pin u-table (larger unique miss stream), stream w-table.
__device__ __forceinline__ unsigned long long make_policy_keep() {
    unsigned long long pol;
    asm("createpolicy.fractional.L2::evict_last.b64 %0, 1.0;" : "=l"(pol));
    return pol;
}
__device__ __forceinline__ unsigned long long make_policy_stream() {
    unsigned long long pol;
    asm("createpolicy.fractional.L2::evict_first.b64 %0, 1.0;" : "=l"(pol));
    return pol;
}
__device__ __forceinline__ float4 ldg_pol(const float4* p, unsigned long long pol) {
    float4 v;
    asm("ld.global.nc.L2::cache_hint.v4.f32 {%0,%1,%2,%3}, [%4], %5;"
        : "=f"(v.x), "=f"(v.y), "=f"(v.z), "=f"(v.w)
        : "l"(p), "l"(pol));
    return v;
}

__global__ __launch_bounds__(THREADS)
void cbow_loss_fused(const int* __restrict__ pos_u,   // [B, CTX]
                     const int* __restrict__ pos_w,   // [B]
                     const int* __restrict__ neg_w,   // [B, NEG]
                     const float4* __restrict__ u_w,  // [VOCAB, 32] as float4
                     const float4* __restrict__ w_w,  // [VOCAB, 32] as float4
                     float* __restrict__ out)
{
    const int warp = threadIdx.x >> 5;
    const int lane = threadIdx.x & 31;
    const int b0 = (blockIdx.x * WARPS_PER_BLOCK + warp) * ELEMS_PER_WARP;

    const unsigned long long pol_keep   = make_policy_keep();
    const unsigned long long pol_stream = make_policy_stream();

    float ls = 0.0f;   // per-lane partial of logsigmoid terms (lane0 holds result)

    #pragma unroll
    for (int e = 0; e < ELEMS_PER_WARP; ++e) {
        const int b = b0 + e;

        // --- gather-sum context embeddings (u-table: keep) ---
        float4 usum = make_float4(0.f, 0.f, 0.f, 0.f);
        const int* pu = pos_u + b * CTX;
        #pragma unroll
        for (int c = 0; c < CTX; ++c) {
            int idx = __ldg(pu + c);                     // uniform across warp
            float4 v = ldg_pol(u_w + (size_t)idx * 32 + lane, pol_keep);
            usum.x += v.x; usum.y += v.y; usum.z += v.z; usum.w += v.w;
        }

        // --- positive target row (w-table: stream) ---
        int pidx = __ldg(pos_w + b);
        float4 p = ldg_pol(w_w + (size_t)pidx * 32 + lane, pol_stream);
        float pd = usum.x * p.x + usum.y * p.y + usum.z * p.z + usum.w * p.w;

        // --- negative rows summed first (dot distributes over the sum) ---
        float4 nsum = make_float4(0.f, 0.f, 0.f, 0.f);
        const int* nw = neg_w + b * NEG;
        #pragma unroll
        for (int k = 0; k < NEG; ++k) {
            int idx = __ldg(nw + k);
            float4 v = ldg_pol(w_w + (size_t)idx * 32 + lane, pol_stream);
            nsum.x += v.x; nsum.y += v.y; nsum.z += v.z; nsum.w += v.w;
        }
        float nd = usum.x * nsum.x + usum.y * nsum.y + usum.z * nsum.z + usum.w * nsum.w;

        // --- warp reduce both dots together ---
        #pragma unroll
        for (int off = 16; off > 0; off >>= 1) {
            pd += __shfl_xor_sync(0xFFFFFFFFu, pd, off);
            nd += __shfl_xor_sync(0xFFFFFFFFu, nd, off);
        }
        if (lane == 0)
            ls += log_sigmoid(pd) + log_sigmoid(-nd);
    }

    __shared__ float s_part[WARPS_PER_BLOCK];
    if (lane == 0)
        s_part[warp] = ls;
    __syncthreads();

    // --- featherweight epilogue: one double atomic per block + ticket ---
    if (threadIdx.x == 0) {
        float acc = 0.f;
        #pragma unroll
        for (int i = 0; i < WARPS_PER_BLOCK; ++i) acc += s_part[i];
        atomicAdd(&g_accum, (double)acc);   // order-insensitive in double
        __threadfence();                    // release before ticket
        unsigned int t = atomicAdd(&g_ticket, 1u);
        if (t == NUM_BLOCKS - 1) {
            __threadfence();                // acquire after last ticket
            double total = g_accum;
            out[0] = (float)(-total);       // loss = -(sum of logsigmoids)
            g_accum  = 0.0;                 // reset for next graph replay
            g_ticket = 0;
        }
    }
}

extern "C" void kernel_launch(void* const* d_in, const int* in_sizes, int n_in,
                              void* d_out, int out_size) {
    const int*    pos_u = (const int*)d_in[0];
    const int*    pos_w = (const int*)d_in[1];
    const int*    neg_w = (const int*)d_in[2];
    const float4* u_w   = (const float4*)d_in[3];
    const float4* w_w   = (const float4*)d_in[4];
    float* out = (float*)d_out;

    cbow_loss_fused<<<NUM_BLOCKS, THREADS>>>(pos_u, pos_w, neg_w, u_w, w_w, out);
}